// round 11
// baseline (speedup 1.0000x reference)
#include <cuda_runtime.h>
#include <cstdint>

#define BB 32
#define NN 16384
#define DD 64
#define SCAP 8192

// Scratch (no allocations allowed)
__device__ float    g_rowsum[BB];
__device__ int      g_k[BB];
__device__ unsigned g_visbits[BB * (NN / 32)];   // 64KB visibility bitmask
__device__ unsigned g_done;

// ---------------------------------------------------------------------------
// k_select_fast: one CTA per row. Fast keys via __logf (MUFU), radix-select
// pivot on fast keys, guard-band classification with exact (accurate logf)
// recompute + stable ranking for the boundary set only. Emits visibility.
// ---------------------------------------------------------------------------
__global__ void __launch_bounds__(1024, 1) k_select_fast(
    const float* __restrict__ u_g, const float* __restrict__ lpt,
    const float* __restrict__ lph, const float* __restrict__ lpw,
    const float* __restrict__ u_k)
{
    extern __shared__ uint32_t sdyn[];           // skey[SCAP], sidx[SCAP] = 64KB
    uint32_t* skey = sdyn;
    uint32_t* sidx = sdyn + SCAP;
    __shared__ unsigned hist[256];
    __shared__ unsigned suf[256];
    __shared__ uint32_t s_thr;
    __shared__ int s_nS, s_A;

    int b = blockIdx.x;
    int tid = threadIdx.x;

    if (tid == 0) {
        g_rowsum[b] = 0.f;
        if (b == 0) g_done = 0u;
        s_nS = 0; s_A = 0;
    }

    // k per row: rates = (u_k + b/31) % 1 ; k = clip(int(N*rates), 1, N-1)
    float r = u_k[0] + (float)b * (1.0f / 31.0f);
    r = r - floorf(r);
    int k = (int)(16384.0f * r);
    k = k < 1 ? 1 : (k > NN - 1 ? NN - 1 : k);
    if (tid == 0) g_k[b] = k;

    float lph_v = lph[b * 32 + (tid >> 5)];
    float lpw_v = lpw[b * 32 + (tid & 31)];
    const float* __restrict__ ug = u_g + ((size_t)b << 14);
    const float* __restrict__ lt = lpt + b * 16;

    // Fast keys (same m association as reference; only the logs are approx).
    float fws[16];
    #pragma unroll
    for (int s = 0; s < 16; s++) {
        float u = ug[s * 1024 + tid];
        float gf = -__logf(-__logf(u));
        fws[s] = gf + ((lt[s] + lph_v) + lpw_v);
    }
    __syncthreads();                              // s_nS/s_A zero visible

    // 4-pass radix select on fast keys (monotone uint map recomputed per use)
    uint32_t prefix = 0, pmask = 0;
    int krem = k;
    for (int pass = 0; pass < 4; pass++) {
        int shift = 24 - 8 * pass;
        if (tid < 256) hist[tid] = 0;
        __syncthreads();
        #pragma unroll
        for (int s = 0; s < 16; s++) {
            uint32_t bits = __float_as_uint(fws[s]);
            uint32_t kk = (bits & 0x80000000u) ? ~bits : (bits | 0x80000000u);
            if ((kk & pmask) == prefix)
                atomicAdd(&hist[(kk >> shift) & 255u], 1u);
        }
        __syncthreads();
        if (tid < 256) suf[tid] = hist[tid];
        __syncthreads();
        for (int d = 1; d < 256; d <<= 1) {       // inclusive suffix sums
            unsigned v = 0;
            if (tid < 256) { v = suf[tid]; if (tid + d < 256) v += suf[tid + d]; }
            __syncthreads();
            if (tid < 256) suf[tid] = v;
            __syncthreads();
        }
        if (tid < 256) {
            int above = (int)(suf[tid] - hist[tid]);
            if (above < krem && krem <= (int)suf[tid]) {
                s_thr = prefix | ((uint32_t)tid << shift);
                atomicExch((int*)&hist[0], 0);    // no-op keep
            }
        }
        __syncthreads();
        // krem update needs the winning bucket's 'above'
        if (tid < 256) {
            uint32_t cand = prefix | ((uint32_t)tid << shift);
            if (cand == s_thr) {
                int above = (int)(suf[tid] - hist[tid]);
                // store krem in suf[0] slot via race-free single writer
                ((volatile int*)&s_nS)[0] = s_nS;  // no-op
                hist[255] = (unsigned)(krem - above);
            }
        }
        __syncthreads();
        krem = (int)hist[255];
        prefix = s_thr;
        pmask |= (0xFFu << shift);
        __syncthreads();
    }

    // pivot (k-th largest fast key) back to float
    uint32_t tk = s_thr;
    uint32_t tbits = (tk & 0x80000000u) ? (tk & 0x7FFFFFFFu) : ~tk;
    float thrF = __uint_as_float(tbits);

    const float Be = 5e-3f;                       // >> fast-log error bound
    float T_hi = thrF + 2.0f * Be;
    float T_lo = thrF - 2.0f * Be;

    // Count A (surely-visible) and build boundary set S with EXACT keys.
    int cA = 0;
    #pragma unroll
    for (int s = 0; s < 16; s++) cA += (fws[s] > T_hi);
    #pragma unroll
    for (int o = 16; o; o >>= 1) cA += __shfl_down_sync(0xffffffffu, cA, o);
    if ((tid & 31) == 0) atomicAdd(&s_A, cA);

    #pragma unroll
    for (int s = 0; s < 16; s++) {
        if (fws[s] >= T_lo && fws[s] <= T_hi) {
            int slot = atomicAdd(&s_nS, 1);
            if (slot < SCAP) {
                int n = s * 1024 + tid;
                float u = ug[n];                  // reload (rare path)
                float ge = -logf(-logf(u));       // ACCURATE, matches reference
                float fe = ge + ((lt[s] + lph_v) + lpw_v);
                uint32_t eb = __float_as_uint(fe);
                skey[slot] = (eb & 0x80000000u) ? ~eb : (eb | 0x80000000u);
                sidx[slot] = (uint32_t)n;         // 14 bits
            }
        }
    }
    __syncthreads();

    int nS = s_nS < SCAP ? s_nS : SCAP;
    int kmA = k - s_A;                            // >= 1 by construction

    // Stable exact rank within S (rank = #{exact greater, or equal w/ lower idx})
    int myrank[SCAP / 1024];
    for (int i = tid, c = 0; i < nS; i += 1024, c++) {
        uint32_t ki = skey[i], ii = sidx[i];
        int rank = 0;
        for (int j = 0; j < nS; j++) {
            uint32_t kj = skey[j];
            rank += (kj > ki) || (kj == ki && sidx[j] < ii);
        }
        myrank[c] = rank;
    }
    __syncthreads();
    for (int i = tid, c = 0; i < nS; i += 1024, c++)
        if (myrank[c] < kmA) sidx[i] |= 0x80000000u;
    __syncthreads();

    // Final visibility + bitmask
    #pragma unroll
    for (int s = 0; s < 16; s++) {
        bool vis = fws[s] > T_hi;
        if (!vis && fws[s] >= T_lo) {
            unsigned n = (unsigned)(s * 1024 + tid);
            for (int j = 0; j < nS; j++) {
                if ((sidx[j] & 0x3FFFu) == n) { vis = (sidx[j] >> 31) != 0u; break; }
            }
        }
        unsigned m = __ballot_sync(0xffffffffu, vis);
        if ((tid & 31) == 0)
            g_visbits[(b << 9) + ((s * 1024 + tid) >> 5)] = m;
    }
}

// ---------------------------------------------------------------------------
// k_mask_final: unchanged from best (R7): half-warp float4 predicated gather,
// blocks round-robin over rows, last block emits the loss.
// ---------------------------------------------------------------------------
__global__ void __launch_bounds__(256) k_mask_final(
    const float* __restrict__ score, float* __restrict__ out, int out_size)
{
    __shared__ float ssum[8];
    __shared__ bool slast;
    int g = blockIdx.x;
    int b = g & 31;
    int chunk = g >> 5;
    int warp = threadIdx.x >> 5, lane = threadIdx.x & 31;
    int tok0 = (b << 14) + chunk * 256 + warp * 32;

    unsigned visword = g_visbits[tok0 >> 5];

    if (out_size >= BB * NN) {
        int off = (out_size > BB * NN) ? 1 : 0;      // loss slot first
        out[off + tok0 + lane] = ((visword >> lane) & 1u) ? 1.0f : 0.0f;
    }

    int sub = lane >> 4;
    const float4* __restrict__ rowsq =
        (const float4*)score + (((size_t)(tok0 + sub)) << 4) + (lane & 15);

    float a0 = 0.f, a1 = 0.f, a2 = 0.f, a3 = 0.f;
    #pragma unroll
    for (int jj = 0; jj < 16; jj += 4) {
        float4 z = make_float4(0.f, 0.f, 0.f, 0.f);
        float4 v0 = z, v1 = z, v2 = z, v3 = z;
        if (!((visword >> (2 * (jj + 0) + sub)) & 1u)) v0 = rowsq[(jj + 0) * 32];
        if (!((visword >> (2 * (jj + 1) + sub)) & 1u)) v1 = rowsq[(jj + 1) * 32];
        if (!((visword >> (2 * (jj + 2) + sub)) & 1u)) v2 = rowsq[(jj + 2) * 32];
        if (!((visword >> (2 * (jj + 3) + sub)) & 1u)) v3 = rowsq[(jj + 3) * 32];
        a0 += (v0.x + v0.y) + (v0.z + v0.w);
        a1 += (v1.x + v1.y) + (v1.z + v1.w);
        a2 += (v2.x + v2.y) + (v2.z + v2.w);
        a3 += (v3.x + v3.y) + (v3.z + v3.w);
    }
    float acc = (a0 + a1) + (a2 + a3);
    #pragma unroll
    for (int o = 16; o; o >>= 1) acc += __shfl_down_sync(0xffffffffu, acc, o);
    if (lane == 0) ssum[warp] = acc;
    __syncthreads();
    if (threadIdx.x == 0) {
        float t = 0.f;
        #pragma unroll
        for (int i = 0; i < 8; i++) t += ssum[i];
        atomicAdd(&g_rowsum[b], t);
        __threadfence();
        unsigned old = atomicAdd(&g_done, 1u);
        slast = (old == gridDim.x - 1);
    }
    __syncthreads();
    if (slast && threadIdx.x < 32) {
        __threadfence();
        float w = g_rowsum[threadIdx.x] *
                  (16384.0f / (float)(NN - g_k[threadIdx.x]));
        #pragma unroll
        for (int o = 16; o; o >>= 1) w += __shfl_down_sync(0xffffffffu, w, o);
        if (threadIdx.x == 0 && out_size != BB * NN)
            out[0] = w / 33554432.0f;                // B*N*D
    }
}

extern "C" void kernel_launch(void* const* d_in, const int* in_sizes, int n_in,
                              void* d_out, int out_size) {
    const float* u_g   = (const float*)d_in[0];
    const float* lpt   = (const float*)d_in[1];
    const float* lph   = (const float*)d_in[2];
    const float* lpw   = (const float*)d_in[3];
    const float* u_k   = (const float*)d_in[4];
    const float* score = (const float*)d_in[5];
    float* out = (float*)d_out;

    cudaFuncSetAttribute(k_select_fast,
                         cudaFuncAttributeMaxDynamicSharedMemorySize, 65536);

    k_select_fast<<<BB, 1024, 65536>>>(u_g, lpt, lph, lpw, u_k);
    k_mask_final<<<BB * NN / 256, 256>>>(score, out, out_size);
}